// round 1
// baseline (speedup 1.0000x reference)
#include <cuda_runtime.h>
#include <cub/cub.cuh>

#define BB 4
#define CIN 1024
#define CMID 512
#define HH 64
#define WW 96
#define AA 9
#define NANCH (AA*HH*WW)      /* 55296 */
#define TOTAL (BB*NANCH)      /* 221184 */
#define PRE 6000
#define POST 300
#define MWORDS 94             /* ceil(6000/64) */

// ---------------- scratch (static device globals; no allocation) -------------
__device__ float g_conv1[(size_t)BB*CMID*HH*WW];          // 50 MB
__device__ float g_wT[(size_t)CIN*9*CMID];                // 18.9 MB  [ci][tap][co]
__device__ float4 g_props[TOTAL];                         // 3.5 MB
__device__ unsigned long long g_keys[TOTAL];
__device__ unsigned long long g_keys_out[TOTAL];
__device__ int g_vals[TOTAL];
__device__ int g_vals_out[TOTAL];
__device__ float4 g_top[BB*PRE];
__device__ unsigned long long g_mask[(size_t)BB*PRE*MWORDS]; // 18 MB
__device__ unsigned char g_temp[32u<<20];                 // cub temp

// base anchor widths/heights (ratio-major, scale-minor) -- exact integers
__constant__ float c_WS[9] = {184.f,368.f,736.f,128.f,256.f,512.f, 88.f,176.f,352.f};
__constant__ float c_HS[9] = { 96.f,192.f,384.f,128.f,256.f,512.f,176.f,352.f,704.f};

// ---------------- K0: transpose conv weights to [ci][tap][co] ---------------
__global__ void transpose_w(const float* __restrict__ conv_w) {
    int idx = blockIdx.x * blockDim.x + threadIdx.x;
    if (idx >= CIN*9*CMID) return;
    int co  = idx % CMID;
    int r   = idx / CMID;
    int tap = r % 9;
    int ci  = r / 9;
    g_wT[idx] = conv_w[((size_t)co*CIN + ci)*9 + tap];
}

// ---------------- K1: 3x3 conv + bias + relu (fp32, smem-tiled) -------------
#define CI_T 8
__global__ __launch_bounds__(256) void conv3x3_relu(const float* __restrict__ feat,
                                                    const float* __restrict__ bias) {
    __shared__ float s_in[CI_T][3][98];   // input row tile (padded)
    __shared__ float s_w[CI_T][9][64];    // weights [ci][tap][co_local]
    const int b   = blockIdx.z;
    const int h   = blockIdx.y;
    const int co0 = blockIdx.x * 64;
    const int t   = threadIdx.x;
    const int cog = t & 15;               // 16 groups of 4 co
    const int wb  = (t >> 4) * 6;         // 16 groups of 6 w

    float acc[4][6];
    #pragma unroll
    for (int c = 0; c < 4; ++c)
        #pragma unroll
        for (int x = 0; x < 6; ++x) acc[c][x] = 0.f;

    const float* fbase = feat + (size_t)b*CIN*HH*WW;

    for (int ci0 = 0; ci0 < CIN; ci0 += CI_T) {
        // load input tile: 8 ci x 3 rows x 98 cols (zero-padded)
        for (int idx = t; idx < CI_T*3*98; idx += 256) {
            int wi = idx % 98;
            int r  = idx / 98;
            int dy = r % 3;
            int ci = r / 3;
            int hh = h + dy - 1;
            int xx = wi - 1;
            float v = 0.f;
            if (hh >= 0 && hh < HH && xx >= 0 && xx < WW)
                v = fbase[((size_t)(ci0+ci)*HH + hh)*WW + xx];
            s_in[ci][dy][wi] = v;
        }
        // load weights (coalesced over co)
        for (int idx = t; idx < CI_T*9*64; idx += 256) {
            int co  = idx & 63;
            int r   = idx >> 6;
            int tap = r % 9;
            int ci  = r / 9;
            s_w[ci][tap][co] = g_wT[((size_t)(ci0+ci)*9 + tap)*CMID + co0 + co];
        }
        __syncthreads();
        #pragma unroll 2
        for (int ci = 0; ci < CI_T; ++ci) {
            #pragma unroll
            for (int dy = 0; dy < 3; ++dy) {
                float iv[8];
                #pragma unroll
                for (int x = 0; x < 8; ++x) iv[x] = s_in[ci][dy][wb + x];
                #pragma unroll
                for (int dx = 0; dx < 3; ++dx) {
                    float4 wv = *(const float4*)&s_w[ci][dy*3+dx][cog*4];
                    #pragma unroll
                    for (int x = 0; x < 6; ++x) {
                        float f = iv[x + dx];
                        acc[0][x] = fmaf(wv.x, f, acc[0][x]);
                        acc[1][x] = fmaf(wv.y, f, acc[1][x]);
                        acc[2][x] = fmaf(wv.z, f, acc[2][x]);
                        acc[3][x] = fmaf(wv.w, f, acc[3][x]);
                    }
                }
            }
        }
        __syncthreads();
    }
    #pragma unroll
    for (int c = 0; c < 4; ++c) {
        int co = co0 + cog*4 + c;
        float bv = bias[co];
        #pragma unroll
        for (int x = 0; x < 6; ++x) {
            float v = acc[c][x] + bv;
            g_conv1[(((size_t)b*CMID + co)*HH + h)*WW + wb + x] = fmaxf(v, 0.f);
        }
    }
}

// -------- K2: 1x1 heads + softmax + anchor decode + clip + sort keys --------
__global__ __launch_bounds__(288) void heads_kernel(const float* __restrict__ cls_w,
                                                    const float* __restrict__ cls_b,
                                                    const float* __restrict__ bbox_w,
                                                    const float* __restrict__ bbox_b,
                                                    const float* __restrict__ im_info) {
    extern __shared__ float sm[];
    float* wsm = sm;                 // [54][512]
    float* fsm = sm + 54*512;        // [64][96]
    const int bh = blockIdx.x;
    const int b  = bh / HH;
    const int h  = bh % HH;
    const int t  = threadIdx.x;      // 288 = 9 anchors x 32 lanes
    const int a    = t / 32;
    const int lane = t % 32;

    for (int i = t; i < 18*512; i += 288) wsm[i] = cls_w[i];
    for (int i = t; i < 36*512; i += 288) wsm[18*512 + i] = bbox_w[i];

    float acc[6][3];
    #pragma unroll
    for (int o = 0; o < 6; ++o)
        #pragma unroll
        for (int q = 0; q < 3; ++q) acc[o][q] = 0.f;

    const float* w0 = wsm + a*512;
    const float* w1 = wsm + (a+9)*512;
    const float* wd = wsm + (18 + a*4)*512;

    for (int ct = 0; ct < 8; ++ct) {
        __syncthreads();
        for (int i = t; i < 64*96; i += 288)
            fsm[i] = g_conv1[(((size_t)b*CMID + ct*64 + i/96)*HH + h)*WW + (i%96)];
        __syncthreads();
        #pragma unroll 4
        for (int cl = 0; cl < 64; ++cl) {
            int ch = ct*64 + cl;
            float v0 = w0[ch], v1 = w1[ch];
            float v2 = wd[ch], v3 = wd[512+ch], v4 = wd[1024+ch], v5 = wd[1536+ch];
            #pragma unroll
            for (int q = 0; q < 3; ++q) {
                float f = fsm[cl*96 + lane + q*32];
                acc[0][q] = fmaf(v0, f, acc[0][q]);
                acc[1][q] = fmaf(v1, f, acc[1][q]);
                acc[2][q] = fmaf(v2, f, acc[2][q]);
                acc[3][q] = fmaf(v3, f, acc[3][q]);
                acc[4][q] = fmaf(v4, f, acc[4][q]);
                acc[5][q] = fmaf(v5, f, acc[5][q]);
            }
        }
    }

    const float imh = im_info[b*3+0] - 1.f;
    const float imw = im_info[b*3+1] - 1.f;
    const float cb0 = cls_b[a], cb1 = cls_b[a+9];
    const float bb0 = bbox_b[a*4+0], bb1 = bbox_b[a*4+1];
    const float bb2 = bbox_b[a*4+2], bb3 = bbox_b[a*4+3];
    const float ws_ = c_WS[a], hs_ = c_HS[a];

    #pragma unroll
    for (int q = 0; q < 3; ++q) {
        int w = lane + q*32;
        float s0 = acc[0][q] + cb0;
        float s1 = acc[1][q] + cb1;
        float m  = fmaxf(s0, s1);
        float e0 = expf(s0 - m), e1 = expf(s1 - m);
        float score = e1 / (e0 + e1);
        float d0 = acc[2][q] + bb0;
        float d1 = acc[3][q] + bb1;
        float d2 = acc[4][q] + bb2;
        float d3 = acc[5][q] + bb3;
        // anchor (exact in fp32)
        float ax1 = 16.f*w + (7.5f - 0.5f*(ws_-1.f));
        float ay1 = 16.f*h + (7.5f - 0.5f*(hs_-1.f));
        float cxa = ax1 + 0.5f*ws_;
        float cya = ay1 + 0.5f*hs_;
        float cx = d0*ws_ + cxa;
        float cy = d1*hs_ + cya;
        float pw = expf(d2)*ws_;
        float ph = expf(d3)*hs_;
        float x1 = cx - 0.5f*pw, y1 = cy - 0.5f*ph;
        float x2 = cx + 0.5f*pw, y2 = cy + 0.5f*ph;
        x1 = fminf(fmaxf(x1, 0.f), imw);
        x2 = fminf(fmaxf(x2, 0.f), imw);
        y1 = fminf(fmaxf(y1, 0.f), imh);
        y2 = fminf(fmaxf(y2, 0.f), imh);
        int pidx = (h*WW + w)*AA + a;
        int gi = b*NANCH + pidx;
        g_props[gi] = make_float4(x1, y1, x2, y2);
        unsigned u = __float_as_uint(score);
        u = (u & 0x80000000u) ? ~u : (u | 0x80000000u);   // ascending-sortable
        g_keys[gi] = ((unsigned long long)b << 32) | (unsigned)(~u); // desc score
        g_vals[gi] = pidx;
    }
}

// ---------------- K3: gather top-6000 boxes per batch -----------------------
__global__ void gather_kernel() {
    int t = blockIdx.x * blockDim.x + threadIdx.x;
    if (t >= BB*PRE) return;
    int b = t / PRE, r = t % PRE;
    int j = g_vals_out[b*NANCH + r];
    g_top[t] = g_props[b*NANCH + j];
}

// ---------------- K4: NMS suppression bitmask (6000x6000 per batch) ---------
__global__ __launch_bounds__(256) void mask_kernel() {
    int t = blockIdx.x * blockDim.x + threadIdx.x;
    if (t >= BB*PRE) return;
    int b = t / PRE;
    float4 bi = g_top[t];
    float ai = (bi.z - bi.x + 1.f) * (bi.w - bi.y + 1.f);
    const float4* base = g_top + b*PRE;
    unsigned long long* mrow = g_mask + (size_t)t*MWORDS;
    unsigned long long word = 0;
    #pragma unroll 4
    for (int j = 0; j < PRE; ++j) {
        float4 bj = __ldg(&base[j]);               // warp-uniform -> broadcast
        float xx1 = fmaxf(bi.x, bj.x), yy1 = fmaxf(bi.y, bj.y);
        float xx2 = fminf(bi.z, bj.z), yy2 = fminf(bi.w, bj.w);
        float iw = fmaxf(xx2 - xx1 + 1.f, 0.f);
        float ih = fmaxf(yy2 - yy1 + 1.f, 0.f);
        float inter = iw * ih;
        float aj = (bj.z - bj.x + 1.f) * (bj.w - bj.y + 1.f);
        float iou = __fdiv_rn(inter, ai + aj - inter);
        if (!(iou <= 0.7f))                        // NaN also suppresses (matches ref)
            word |= (1ULL << (j & 63));
        if ((j & 63) == 63) { mrow[j >> 6] = word; word = 0; }
    }
    mrow[MWORDS - 1] = word;                       // tail (bits 0..47)
}

// ---------------- K5: warp-sequential greedy NMS scan + roi write -----------
__device__ __forceinline__ unsigned long long shfl64(unsigned long long v, int src) {
    return __shfl_sync(0xffffffffu, v, src);
}

__global__ void nms_scan(float* __restrict__ out) {
    const int b = blockIdx.x;
    const int lane = threadIdx.x;                  // 32 threads
    __shared__ int keeps[POST];
    const unsigned long long* mbase = g_mask + (size_t)b*PRE*MWORDS;
    unsigned long long r0 = 0, r1 = 0, r2 = 0;     // removed bitmap, 94 words
    int cnt = 0;
    for (int w = 0; w < MWORDS && cnt < POST; ++w) {
        int src = w & 31;
        unsigned long long cur = (w < 32) ? r0 : (w < 64 ? r1 : r2);
        unsigned long long val = shfl64(cur, src);
        unsigned long long avail = ~val;
        if (w == MWORDS - 1) avail &= (1ULL << 48) - 1;   // bits past 5999 invalid
        while (avail && cnt < POST) {
            int bit = __ffsll((long long)avail) - 1;
            int i = (w << 6) + bit;
            keeps[cnt++] = i;
            const unsigned long long* row = mbase + (size_t)i*MWORDS;
            r0 |= row[lane];
            r1 |= row[lane + 32];
            if (lane < 30) r2 |= row[lane + 64];
            unsigned long long cur2 = (w < 32) ? r0 : (w < 64 ? r1 : r2);
            avail &= ~shfl64(cur2, src);
        }
    }
    __syncwarp();
    for (int k = lane; k < POST; k += 32) {
        float4 bx = make_float4(0.f, 0.f, 0.f, 0.f);
        if (k < cnt) bx = g_top[b*PRE + keeps[k]];
        float* o = out + ((size_t)b*POST + k)*5;
        o[0] = (float)b; o[1] = bx.x; o[2] = bx.y; o[3] = bx.z; o[4] = bx.w;
    }
}

// -----------------------------------------------------------------------------
extern "C" void kernel_launch(void* const* d_in, const int* in_sizes, int n_in,
                              void* d_out, int out_size) {
    const float* base_feat = (const float*)d_in[0];
    const float* im_info   = (const float*)d_in[1];
    const float* conv_w    = (const float*)d_in[4];
    const float* conv_b    = (const float*)d_in[5];
    const float* cls_w     = (const float*)d_in[6];
    const float* cls_b     = (const float*)d_in[7];
    const float* bbox_w    = (const float*)d_in[8];
    const float* bbox_b    = (const float*)d_in[9];
    float* out = (float*)d_out;

    transpose_w<<<(CIN*9*CMID + 255)/256, 256>>>(conv_w);

    dim3 cgrid(CMID/64, HH, BB);
    conv3x3_relu<<<cgrid, 256>>>(base_feat, conv_b);

    size_t hsmem = (size_t)(54*512 + 64*96) * sizeof(float);   // ~132 KB
    cudaFuncSetAttribute(heads_kernel, cudaFuncAttributeMaxDynamicSharedMemorySize,
                         (int)hsmem);
    heads_kernel<<<BB*HH, 288, hsmem>>>(cls_w, cls_b, bbox_w, bbox_b, im_info);

    void *d_temp, *dk, *dko, *dv, *dvo;
    cudaGetSymbolAddress(&d_temp, g_temp);
    cudaGetSymbolAddress(&dk,  g_keys);
    cudaGetSymbolAddress(&dko, g_keys_out);
    cudaGetSymbolAddress(&dv,  g_vals);
    cudaGetSymbolAddress(&dvo, g_vals_out);
    size_t temp_bytes = sizeof(g_temp);
    cub::DeviceRadixSort::SortPairs(d_temp, temp_bytes,
        (const unsigned long long*)dk, (unsigned long long*)dko,
        (const int*)dv, (int*)dvo, TOTAL, 0, 34, (cudaStream_t)0);

    gather_kernel<<<(BB*PRE + 255)/256, 256>>>();
    mask_kernel<<<(BB*PRE + 255)/256, 256>>>();
    nms_scan<<<BB, 32>>>(out);
    (void)in_sizes; (void)n_in; (void)out_size;
}